// round 14
// baseline (speedup 1.0000x reference)
#include <cuda_runtime.h>
#include <cuda_bf16.h>
#include <stdint.h>
#include <math.h>
#include <mma.h>

using namespace nvcuda;

#define BB   128
#define TT   256
#define SS   64
#define IIN  3
#define HH   512
#define KK   10
#define CSL  60
#define OUTD 121
#define G4   2048
#define K1TOT 575
#define K2TOT 512
#define NBLK 128
#define K1PAD 576

// ---------------- scratch ------------------------------------------------------
__device__ float g_h1T[2][HH*BB + 64];          // [parity][h][b]
__device__ float g_h2T[2][HH*BB + 64];
__device__ float g_winT[CSL*BB];                // [c][b]
__device__ float g_l2inT[(size_t)TT*G4*BB];     // [t][j][b]
__device__ float g_h1f[BB*HH], g_c1f[BB*HH], g_h2f[BB*HH], g_c2f[BB*HH];

// bf16 hi/lo operand buffers for HMMA GEMMs
__device__ __nv_bfloat16 g_feat_h[(size_t)TT*BB*K1PAD];   // [t*128+b][576] (x|win|h|pad)
__device__ __nv_bfloat16 g_feat_l[(size_t)TT*BB*K1PAD];
__device__ __nv_bfloat16 g_y_h[(size_t)TT*BB*K2TOT];      // [t*128+b][512]
__device__ __nv_bfloat16 g_y_l[(size_t)TT*BB*K2TOT];
__device__ __nv_bfloat16 g_wl_h[(size_t)G4*K1PAD];        // Wihl split, col 575 = 0
__device__ __nv_bfloat16 g_wl_l[(size_t)G4*K1PAD];
__device__ __nv_bfloat16 g_wo_h[128*K2TOT];               // W2 split, rows >=121 zero
__device__ __nv_bfloat16 g_wo_l[128*K2TOT];

// ---------------- grid barrier -------------------------------------------------
__device__ unsigned g_cnt = 0;
__device__ volatile unsigned g_gen = 0;

__device__ __forceinline__ void gbar()
{
    __syncthreads();
    if (threadIdx.x == 0){
        unsigned my = g_gen;
        __threadfence();
        if (atomicAdd(&g_cnt, 1u) == NBLK-1u){
            g_cnt = 0;
            __threadfence();
            g_gen = my + 1u;
        } else {
            while (g_gen == my) __nanosleep(64);
        }
        __threadfence();
    }
    __syncthreads();
}

__device__ __forceinline__ float sigf(float x){ return 1.0f/(1.0f+expf(-x)); }

__device__ __forceinline__ void bsplit(float v, __nv_bfloat16* hp, __nv_bfloat16* lp){
    __nv_bfloat16 h = __float2bfloat16(v);
    *hp = h;
    *lp = __float2bfloat16(v - __bfloat162float(h));
}

// ---------------- cp.async helpers --------------------------------------------
__device__ __forceinline__ void cpa4(void* dst, const void* src){
    unsigned d = (unsigned)__cvta_generic_to_shared(dst);
    asm volatile("cp.async.ca.shared.global [%0], [%1], 4;" :: "r"(d), "l"(src));
}
__device__ __forceinline__ void cpa16(void* dst, const void* src){
    unsigned d = (unsigned)__cvta_generic_to_shared(dst);
    asm volatile("cp.async.ca.shared.global [%0], [%1], 16;" :: "r"(d), "l"(src));
}
__device__ __forceinline__ void cpcommit(){ asm volatile("cp.async.commit_group;"); }
__device__ __forceinline__ void cpwait0(){ asm volatile("cp.async.wait_group 0;"); }
__device__ __forceinline__ void cpwait1(){ asm volatile("cp.async.wait_group 1;"); }

// ---------------- init ---------------------------------------------------------
__global__ void k_init(const float* __restrict__ h1h, const float* __restrict__ h2h)
{
    int i = blockIdx.x*blockDim.x + threadIdx.x;
    if (i < BB*HH){
        int b = i/HH, h = i%HH;
        g_h1T[0][h*BB+b] = h1h[i];
        g_h2T[0][h*BB+b] = h2h[i];
    }
}

// ---------------- convert weights + x columns to bf16 hi/lo --------------------
__global__ void k_cvt(const float* __restrict__ Wihl, const float* __restrict__ W2,
                      const float* __restrict__ x)
{
    const int n1 = G4*K1TOT;          // Wihl
    const int n2 = OUTD*K2TOT;        // W2
    const int n3 = TT*BB*IIN;         // x columns of feat
    const int n4 = TT*BB;             // zero feat pad col (k=575)
    const int n5 = (128-OUTD)*K2TOT;  // zero W2 pad rows
    int total = n1 + n2 + n3 + n4 + n5;
    for (int i = blockIdx.x*blockDim.x + threadIdx.x; i < total; i += gridDim.x*blockDim.x){
        if (i < n1){
            int j = i / K1TOT, k = i % K1TOT;
            bsplit(Wihl[i], &g_wl_h[(size_t)j*K1PAD + k], &g_wl_l[(size_t)j*K1PAD + k]);
        } else if (i < n1 + n2){
            int i2 = i - n1;
            bsplit(W2[i2], &g_wo_h[i2], &g_wo_l[i2]);
        } else if (i < n1 + n2 + n3){
            int i3 = i - n1 - n2;
            int m = i3 / IIN, c = i3 % IIN;
            int b = m & 127, t = m >> 7;
            bsplit(x[((size_t)b*TT + t)*IIN + c],
                   &g_feat_h[(size_t)m*K1PAD + c], &g_feat_l[(size_t)m*K1PAD + c]);
        } else if (i < n1 + n2 + n3 + n4){
            int m = i - n1 - n2 - n3;
            g_feat_h[(size_t)m*K1PAD + 575] = __float2bfloat16(0.f);
            g_feat_l[(size_t)m*K1PAD + 575] = __float2bfloat16(0.f);
        } else {
            int i5 = i - n1 - n2 - n3 - n4;
            g_wo_h[(size_t)OUTD*K2TOT + i5] = __float2bfloat16(0.f);
            g_wo_l[(size_t)OUTD*K2TOT + i5] = __float2bfloat16(0.f);
        }
    }
}

// ================= bf16-split wmma GEMM (M=128, N=128, K=nch*64) ==============
// 512 threads = 16 warps (4x4), warp tile 32x32 (2x2 wmma 16x16x16 frags).
// SMEM: 2 stages x (Ah|Al|Wh|Wl, each 128x64 bf16 = 16KB) = 128KB.
// D = A@W^T with A[m][k] (row-major, stride astr), W[n][k] (row-major, stride wstr).
// 3-product split: ah*wh + ah*wl + al*wh, fp32 accumulate.
__device__ __forceinline__ void wmma_gemm(
    const __nv_bfloat16* __restrict__ Ah, const __nv_bfloat16* __restrict__ Al,
    size_t astr,
    const __nv_bfloat16* __restrict__ Wh, const __nv_bfloat16* __restrict__ Wl,
    size_t wstr,
    int nch, char* smraw, float* Cs, wmma::layout_t clay)
{
    __nv_bfloat16* st = (__nv_bfloat16*)smraw;      // stage s at s*32768 elems
    const int tid = threadIdx.x;
    const int w  = tid >> 5;
    const int wm = w & 3, wn = w >> 2;

    wmma::fragment<wmma::accumulator,16,16,16,float> acc[2][2];
    #pragma unroll
    for (int i=0;i<2;i++)
        #pragma unroll
        for (int j=0;j<2;j++) wmma::fill_fragment(acc[i][j], 0.f);

    const __nv_bfloat16* srcs[4] = {Ah, Al, Wh, Wl};
    const size_t strs[4] = {astr, astr, wstr, wstr};

    // preload chunks 0,1
    #pragma unroll
    for (int c = 0; c < 2; c++){
        __nv_bfloat16* sb = st + c*32768;
        #pragma unroll
        for (int tile = 0; tile < 4; tile++){
            __nv_bfloat16* tb = sb + tile*8192;
            const __nv_bfloat16* bp = srcs[tile] + (size_t)c*64;
            for (int q = tid; q < 1024; q += 512){
                int m = q >> 3, i = q & 7;
                cpa16(tb + m*64 + i*8, bp + (size_t)m*strs[tile] + i*8);
            }
        }
        cpcommit();
    }

    for (int c = 0; c < nch; c++){
        if (c+1 < nch) cpwait1(); else cpwait0();
        __syncthreads();
        __nv_bfloat16* sb = st + (c&1)*32768;
        __nv_bfloat16* At_h = sb;
        __nv_bfloat16* At_l = sb + 8192;
        __nv_bfloat16* Wt_h = sb + 16384;
        __nv_bfloat16* Wt_l = sb + 24576;
        #pragma unroll
        for (int ks = 0; ks < 4; ks++){
            wmma::fragment<wmma::matrix_a,16,16,16,__nv_bfloat16,wmma::row_major> ah[2], al[2];
            #pragma unroll
            for (int i=0;i<2;i++){
                wmma::load_matrix_sync(ah[i], At_h + (wm*32 + i*16)*64 + ks*16, 64);
                wmma::load_matrix_sync(al[i], At_l + (wm*32 + i*16)*64 + ks*16, 64);
            }
            #pragma unroll
            for (int j=0;j<2;j++){
                wmma::fragment<wmma::matrix_b,16,16,16,__nv_bfloat16,wmma::col_major> bh, blo;
                wmma::load_matrix_sync(bh,  Wt_h + (wn*32 + j*16)*64 + ks*16, 64);
                wmma::load_matrix_sync(blo, Wt_l + (wn*32 + j*16)*64 + ks*16, 64);
                #pragma unroll
                for (int i=0;i<2;i++){
                    wmma::mma_sync(acc[i][j], ah[i], bh,  acc[i][j]);
                    wmma::mma_sync(acc[i][j], ah[i], blo, acc[i][j]);
                    wmma::mma_sync(acc[i][j], al[i], bh,  acc[i][j]);
                }
            }
        }
        __syncthreads();
        if (c+2 < nch){
            int cc = c+2;
            __nv_bfloat16* sb2 = st + (cc&1)*32768;
            #pragma unroll
            for (int tile = 0; tile < 4; tile++){
                __nv_bfloat16* tb = sb2 + tile*8192;
                const __nv_bfloat16* bp = srcs[tile] + (size_t)cc*64;
                for (int q = tid; q < 1024; q += 512){
                    int m = q >> 3, i = q & 7;
                    cpa16(tb + m*64 + i*8, bp + (size_t)m*strs[tile] + i*8);
                }
            }
            cpcommit();
        }
    }

    // store C tiles (Cs overlaps stage memory; all SMEM reads are done)
    #pragma unroll
    for (int i=0;i<2;i++)
        #pragma unroll
        for (int j=0;j<2;j++){
            int m0 = wm*32 + i*16, n0 = wn*32 + j*16;
            float* p = (clay == wmma::mem_col_major) ? Cs + n0*128 + m0
                                                     : Cs + m0*128 + n0;
            wmma::store_matrix_sync(p, acc[i][j], 128, clay);
        }
    __syncthreads();
}

// ---------------- l2in: D[t*128+b][2048] = feat @ Wihl^T (HMMA) ----------------
__global__ void __launch_bounds__(512,1) k_l2in_mma(const float* __restrict__ bl)
{
    extern __shared__ char smraw[];
    const int tid = threadIdx.x;
    const int t = blockIdx.y, j0 = blockIdx.x*128;
    float* Cs = (float*)smraw;                       // col-major: Cs[j*128+b]

    wmma_gemm(g_feat_h + (size_t)t*BB*K1PAD, g_feat_l + (size_t)t*BB*K1PAD, K1PAD,
              g_wl_h + (size_t)j0*K1PAD,     g_wl_l + (size_t)j0*K1PAD,     K1PAD,
              9, smraw, Cs, wmma::mem_col_major);

    for (int idx = tid; idx < 128*128; idx += 512){
        int j = idx >> 7, b = idx & 127;
        g_l2inT[((size_t)t*G4 + j0 + j)*BB + b] = Cs[idx] + bl[j0 + j];
    }
}

// ---------------- output projection (HMMA) -------------------------------------
__global__ void __launch_bounds__(512,1) k_out_mma(const float* __restrict__ b2,
                                                   float* __restrict__ out)
{
    extern __shared__ char smraw[];
    const int tid = threadIdx.x;
    const int t = blockIdx.x;
    float* Cs = (float*)smraw;                       // row-major: Cs[b*128+j]

    wmma_gemm(g_y_h + (size_t)t*BB*K2TOT, g_y_l + (size_t)t*BB*K2TOT, K2TOT,
              g_wo_h, g_wo_l, K2TOT,
              8, smraw, Cs, wmma::mem_row_major);

    for (int idx = tid; idx < 128*128; idx += 512){
        int b = idx >> 7, j = idx & 127;
        if (j < OUTD) out[((size_t)b*TT + t)*OUTD + j] = Cs[idx] + b2[j];
    }
}

// ================= persistent layer-1 =========================================
__global__ void __launch_bounds__(512,1)
k_rec1(const float* __restrict__ x,    const float* __restrict__ Wihc,
       const float* __restrict__ Whhc, const float* __restrict__ bc,
       const float* __restrict__ W1,   const float* __restrict__ b1,
       const float* __restrict__ sent, const float* __restrict__ h1c_in)
{
    extern __shared__ float sm[];
    float* Ws    = sm;
    float* As    = Ws + 576*8*4;
    float* sentS = As + 8192;
    float* sh    = sentS + 3840;
    float* sp    = sh + 512;
    float* sphi  = sp + 32;

    const int tid = threadIdx.x;
    const int blk = blockIdx.x;
    const int ht = blk >> 1, bt = blk & 1;
    const int h0 = ht*8;
    const int hl = tid >> 6, bl = tid & 63;
    const int hg = h0 + hl;
    const int bG = bt*64 + bl;
    const int b  = blk;

    for (int idx = tid; idx < 576*8*4; idx += 512){
        int g = idx & 3, h = (idx>>2)&7, k = idx>>5;
        float v = 0.f;
        if (k < K1TOT){
            int j = g*512 + h0 + h;
            v = (k < 63) ? Wihc[(size_t)j*63 + k] : Whhc[(size_t)j*512 + (k-63)];
        }
        Ws[idx] = v;
    }
    for (int idx = tid; idx < SS*CSL; idx += 512)
        sentS[idx] = sent[(size_t)b*SS*CSL + idx];
    if (tid < 32) sp[tid] = 0.f;

    float c1r = h1c_in[(size_t)bG*HH + hg];
    const float bi = bc[hg], bf = bc[512+hg], bg2 = bc[1024+hg], bo = bc[1536+hg];
    __syncthreads();

    const float4* Wsv = (const float4*)Ws;

    for (int t = 0; t < TT; t++){
        const float* h1cur = g_h1T[t&1];

        sh[tid] = h1cur[tid*BB + b];
        __syncthreads();
        {
            int w = tid>>5, lane = tid&31;
            for (int j = w; j < 30; j += 16){
                float s = 0.f;
                #pragma unroll 8
                for (int k = lane; k < 512; k += 32) s += sh[k]*W1[j*512+k];
                #pragma unroll
                for (int o=16;o;o>>=1) s += __shfl_down_sync(0xffffffffu, s, o);
                if (lane == 0){
                    float v = expf(s + b1[j]);
                    if (j >= 20) v -= sp[j];
                    sp[j] = v;
                }
            }
        }
        __syncthreads();
        if (tid < SS){
            float u = (float)(tid+1), acc = 0.f;
            #pragma unroll
            for (int k=0;k<KK;k++){
                float d = sp[20+k] - u;
                acc += sp[k]*expf(-sp[10+k]*d*d);
            }
            sphi[tid] = acc;
        }
        __syncthreads();
        if (tid < CSL){
            float acc = 0.f;
            #pragma unroll 8
            for (int s=0;s<SS;s++) acc += sphi[s]*sentS[s*CSL + tid];
            g_winT[tid*BB + b] = acc;
            size_t mrow = ((size_t)t*BB + b)*K1PAD;
            bsplit(acc, &g_feat_h[mrow + 3 + tid], &g_feat_l[mrow + 3 + tid]);
        }
        gbar();

        float gi = bi, gf = bf, gg = bg2, go = bo;

        for (int idx = tid; idx < 63*64; idx += 512){
            int kk = idx >> 6, bb = bt*64 + (idx & 63);
            const float* src = (kk < 3) ? &x[((size_t)bb*TT + t)*IIN + kk]
                                        : &g_winT[(kk-3)*BB + bb];
            cpa4(&As[idx], src);
        }
        cpcommit();
        for (int q = tid; q < 1024; q += 512){
            int kk = q >> 4, r = q & 15;
            cpa16(&As[4096 + kk*64 + r*4], &h1cur[kk*BB + bt*64 + r*4]);
        }
        cpcommit();

        for (int c = 0; c <= 8; c++){
            if (c == 8) cpwait0(); else cpwait1();
            __syncthreads();
            const float* Ab = As + (c&1)*4096;
            const int klen = c ? 64 : 63;
            const int kof  = c ? 63 + (c-1)*64 : 0;
            #pragma unroll 4
            for (int kk = 0; kk < klen; kk++){
                float  a = Ab[kk*64 + bl];
                float4 w = Wsv[(kof+kk)*8 + hl];
                gi += a*w.x; gf += a*w.y; gg += a*w.z; go += a*w.w;
            }
            __syncthreads();
            if (c+2 <= 8){
                int cc = c+2;
                float* dst = As + (c&1)*4096;
                for (int q = tid; q < 1024; q += 512){
                    int kk = q >> 4, r = q & 15;
                    cpa16(&dst[kk*64 + r*4], &h1cur[((cc-1)*64 + kk)*BB + bt*64 + r*4]);
                }
                cpcommit();
            }
        }

        float cn = sigf(gf)*c1r + sigf(gi)*tanhf(gg);
        float hn = sigf(go)*tanhf(cn);
        c1r = cn;
        g_h1T[(t+1)&1][hg*BB + bG] = hn;
        {
            size_t mrow = ((size_t)t*BB + bG)*K1PAD;
            bsplit(hn, &g_feat_h[mrow + 63 + hg], &g_feat_l[mrow + 63 + hg]);
        }
        if (t == TT-1){
            g_h1f[(size_t)bG*HH + hg] = hn;
            g_c1f[(size_t)bG*HH + hg] = cn;
        }
        gbar();
    }
}

// ================= persistent layer-2 =========================================
__global__ void __launch_bounds__(512,1)
k_rec2(const float* __restrict__ Whhl, const float* __restrict__ h2c_in)
{
    extern __shared__ float sm[];
    float* Ws = sm;
    float* As = Ws + 16384;

    const int tid = threadIdx.x;
    const int blk = blockIdx.x;
    const int ht = blk >> 1, bt = blk & 1;
    const int h0 = ht*8;
    const int hl = tid >> 6, bl = tid & 63;
    const int hg = h0 + hl;
    const int bG = bt*64 + bl;

    for (int idx = tid; idx < 512*8*4; idx += 512){
        int g = idx & 3, h = (idx>>2)&7, k = idx>>5;
        Ws[idx] = Whhl[(size_t)(g*512 + h0 + h)*K2TOT + k];
    }
    float c2r = h2c_in[(size_t)bG*HH + hg];
    __syncthreads();

    const float4* Wsv = (const float4*)Ws;

    for (int t = 0; t < TT; t++){
        const float* h2cur = g_h2T[t&1];

        const float* li = &g_l2inT[(size_t)t*G4*BB];
        float gi = li[(size_t)(hg       )*BB + bG];
        float gf = li[(size_t)(hg +  512)*BB + bG];
        float gg = li[(size_t)(hg + 1024)*BB + bG];
        float go = li[(size_t)(hg + 1536)*BB + bG];

        for (int q = tid; q < 1024; q += 512){
            int kk = q >> 4, r = q & 15;
            cpa16(&As[kk*64 + r*4], &h2cur[kk*BB + bt*64 + r*4]);
        }
        cpcommit();
        for (int q = tid; q < 1024; q += 512){
            int kk = q >> 4, r = q & 15;
            cpa16(&As[4096 + kk*64 + r*4], &h2cur[(64+kk)*BB + bt*64 + r*4]);
        }
        cpcommit();

        for (int c = 0; c <= 7; c++){
            if (c == 7) cpwait0(); else cpwait1();
            __syncthreads();
            const float* Ab = As + (c&1)*4096;
            const int kof = c*64;
            #pragma unroll 4
            for (int kk = 0; kk < 64; kk++){
                float  a = Ab[kk*64 + bl];
                float4 w = Wsv[(kof+kk)*8 + hl];
                gi += a*w.x; gf += a*w.y; gg += a*w.z; go += a*w.w;
            }
            __syncthreads();
            if (c+2 <= 7){
                int cc = c+2;
                float* dst = As + (c&1)*4096;
                for (int q = tid; q < 1024; q += 512){
                    int kk = q >> 4, r = q & 15;
                    cpa16(&dst[kk*64 + r*4], &h2cur[(cc*64 + kk)*BB + bt*64 + r*4]);
                }
                cpcommit();
            }
        }

        float cn = sigf(gf)*c2r + sigf(gi)*tanhf(gg);
        float hn = sigf(go)*tanhf(cn);
        c2r = cn;
        g_h2T[(t+1)&1][hg*BB + bG] = hn;
        {
            size_t mrow = ((size_t)t*BB + bG)*K2TOT;
            bsplit(hn, &g_y_h[mrow + hg], &g_y_l[mrow + hg]);
        }
        if (t == TT-1){
            g_h2f[(size_t)bG*HH + hg] = hn;
            g_c2f[(size_t)bG*HH + hg] = cn;
        }
        gbar();
    }
}

// ---------------- final states -------------------------------------------------
__global__ void k_states(float* __restrict__ out, int out_size)
{
    const int base = BB*TT*OUTD;
    if (base + 4*BB*HH > out_size) return;
    int i = blockIdx.x*256 + threadIdx.x;
    if (i < BB*HH){
        out[base            + i] = g_h1f[i];
        out[base +   BB*HH  + i] = g_c1f[i];
        out[base + 2*BB*HH  + i] = g_h2f[i];
        out[base + 3*BB*HH  + i] = g_c2f[i];
    }
}

// ---------------- launch -------------------------------------------------------
extern "C" void kernel_launch(void* const* d_in, const int* in_sizes, int n_in,
                              void* d_out, int out_size)
{
    const float* x    = (const float*)d_in[0];
    const float* sent = (const float*)d_in[1];
    const float* h1h  = (const float*)d_in[2];
    const float* h1c  = (const float*)d_in[3];
    const float* h2h  = (const float*)d_in[4];
    const float* h2c  = (const float*)d_in[5];
    const float* Wihc = (const float*)d_in[6];
    const float* Whhc = (const float*)d_in[7];
    const float* bc   = (const float*)d_in[8];
    const float* Wihl = (const float*)d_in[9];
    const float* Whhl = (const float*)d_in[10];
    const float* bl   = (const float*)d_in[11];
    const float* W1   = (const float*)d_in[12];
    const float* b1   = (const float*)d_in[13];
    const float* W2   = (const float*)d_in[14];
    const float* b2   = (const float*)d_in[15];
    float* out = (float*)d_out;

    const int SMEM1 = (18432 + 8192 + 3840 + 512 + 32 + 64) * 4;
    const int SMEM2 = (16384 + 8192) * 4;
    const int SMEMP = 2*65536;                    // 2-stage wmma pipeline (128KB)
    cudaFuncSetAttribute(k_rec1, cudaFuncAttributeMaxDynamicSharedMemorySize, SMEM1);
    cudaFuncSetAttribute(k_rec2, cudaFuncAttributeMaxDynamicSharedMemorySize, SMEM2);
    cudaFuncSetAttribute(k_l2in_mma, cudaFuncAttributeMaxDynamicSharedMemorySize, SMEMP);
    cudaFuncSetAttribute(k_out_mma, cudaFuncAttributeMaxDynamicSharedMemorySize, SMEMP);

    k_init<<<256,256>>>(h1h, h2h);
    k_cvt<<<1024,256>>>(Wihl, W2, x);
    k_rec1<<<NBLK,512,SMEM1>>>(x, Wihc, Whhc, bc, W1, b1, sent, h1c);
    k_l2in_mma<<<dim3(16,TT),512,SMEMP>>>(bl);
    k_rec2<<<NBLK,512,SMEM2>>>(Whhl, h2c);
    k_out_mma<<<TT,512,SMEMP>>>(b2, out);
    k_states<<<(BB*HH+255)/256,256>>>(out, out_size);
}

// round 15
// speedup vs baseline: 1.0586x; 1.0586x over previous
#include <cuda_runtime.h>
#include <cuda_bf16.h>
#include <stdint.h>
#include <math.h>
#include <mma.h>

using namespace nvcuda;

#define BB   128
#define TT   256
#define SS   64
#define IIN  3
#define HH   512
#define KK   10
#define CSL  60
#define OUTD 121
#define G4   2048
#define K1TOT 575
#define K2TOT 512
#define NBLK 128
#define K1PAD 576

// ---------------- scratch (fp32, recurrence-side; all coalesced writes) --------
__device__ float g_h1T[2][HH*BB + 64];          // [parity][h][b]
__device__ float g_h2T[2][HH*BB + 64];
__device__ float g_winT[CSL*BB];                // [c][b]
__device__ float g_winsT[TT*CSL*BB];            // [t][c][b]
__device__ float g_hxT[(size_t)TT*HH*BB];       // [t][h][b]
__device__ float g_yT[(size_t)TT*HH*BB];        // [t][h][b]
__device__ float g_l2inT[(size_t)TT*G4*BB];     // [t][j][b]
__device__ float g_h1f[BB*HH], g_c1f[BB*HH], g_h2f[BB*HH], g_c2f[BB*HH];

// bf16 hi/lo operand buffers (zero-initialized by runtime; pads stay zero)
__device__ __nv_bfloat16 g_featT_h[(size_t)TT*K1PAD*BB];  // [t][k][b]
__device__ __nv_bfloat16 g_featT_l[(size_t)TT*K1PAD*BB];
__device__ __nv_bfloat16 g_yT_h[(size_t)TT*K2TOT*BB];     // [t][k][b]
__device__ __nv_bfloat16 g_yT_l[(size_t)TT*K2TOT*BB];
__device__ __nv_bfloat16 g_wl_h[(size_t)G4*K1PAD];        // [j][k], col 575 = 0
__device__ __nv_bfloat16 g_wl_l[(size_t)G4*K1PAD];
__device__ __nv_bfloat16 g_wo_h[128*K2TOT];               // [j][k], rows >=121 zero
__device__ __nv_bfloat16 g_wo_l[128*K2TOT];

// ---------------- grid barrier -------------------------------------------------
__device__ unsigned g_cnt = 0;
__device__ volatile unsigned g_gen = 0;

__device__ __forceinline__ void gbar()
{
    __syncthreads();
    if (threadIdx.x == 0){
        unsigned my = g_gen;
        __threadfence();
        if (atomicAdd(&g_cnt, 1u) == NBLK-1u){
            g_cnt = 0;
            __threadfence();
            g_gen = my + 1u;
        } else {
            while (g_gen == my) __nanosleep(64);
        }
        __threadfence();
    }
    __syncthreads();
}

__device__ __forceinline__ float sigf(float x){ return 1.0f/(1.0f+expf(-x)); }

__device__ __forceinline__ void bsplit(float v, __nv_bfloat16* hp, __nv_bfloat16* lp){
    __nv_bfloat16 h = __float2bfloat16(v);
    *hp = h;
    *lp = __float2bfloat16(v - __bfloat162float(h));
}

// ---------------- cp.async helpers --------------------------------------------
__device__ __forceinline__ void cpa4(void* dst, const void* src){
    unsigned d = (unsigned)__cvta_generic_to_shared(dst);
    asm volatile("cp.async.ca.shared.global [%0], [%1], 4;" :: "r"(d), "l"(src));
}
__device__ __forceinline__ void cpa16(void* dst, const void* src){
    unsigned d = (unsigned)__cvta_generic_to_shared(dst);
    asm volatile("cp.async.ca.shared.global [%0], [%1], 16;" :: "r"(d), "l"(src));
}
__device__ __forceinline__ void cpcommit(){ asm volatile("cp.async.commit_group;"); }
__device__ __forceinline__ void cpwait0(){ asm volatile("cp.async.wait_group 0;"); }
__device__ __forceinline__ void cpwait1(){ asm volatile("cp.async.wait_group 1;"); }

// ---------------- init ---------------------------------------------------------
__global__ void k_init(const float* __restrict__ h1h, const float* __restrict__ h2h)
{
    int i = blockIdx.x*blockDim.x + threadIdx.x;
    if (i < BB*HH){
        int b = i/HH, h = i%HH;
        g_h1T[0][h*BB+b] = h1h[i];
        g_h2T[0][h*BB+b] = h2h[i];
    }
}

// ---------------- convert weights to bf16 hi/lo --------------------------------
__global__ void k_cvt_w(const float* __restrict__ Wihl, const float* __restrict__ W2)
{
    const int n1 = G4*K1TOT;
    const int n2 = OUTD*K2TOT;
    int total = n1 + n2;
    for (int i = blockIdx.x*blockDim.x + threadIdx.x; i < total; i += gridDim.x*blockDim.x){
        if (i < n1){
            int j = i / K1TOT, k = i % K1TOT;
            bsplit(Wihl[i], &g_wl_h[(size_t)j*K1PAD + k], &g_wl_l[(size_t)j*K1PAD + k]);
        } else {
            int i2 = i - n1;
            bsplit(W2[i2], &g_wo_h[i2], &g_wo_l[i2]);
        }
    }
}

// ---------------- feat [t][k][b] fp32 -> bf16 hi/lo (both sides coalesced) -----
__global__ void __launch_bounds__(256) k_cvt_feat(const float* __restrict__ x)
{
    const int t = blockIdx.x;
    for (int idx = threadIdx.x; idx < K1PAD*BB; idx += 256){
        int k = idx >> 7, b = idx & 127;
        float v = 0.f;
        if      (k < IIN)   v = x[((size_t)b*TT + t)*IIN + k];
        else if (k < 63)    v = g_winsT[((size_t)t*CSL + (k-IIN))*BB + b];
        else if (k < K1TOT) v = g_hxT[((size_t)t*HH + (k-63))*BB + b];
        size_t o = (size_t)t*K1PAD*BB + idx;
        bsplit(v, &g_featT_h[o], &g_featT_l[o]);
    }
}

__global__ void __launch_bounds__(256) k_cvt_y()
{
    const int t = blockIdx.x;
    for (int idx = threadIdx.x; idx < K2TOT*BB; idx += 256){
        size_t o = (size_t)t*K2TOT*BB + idx;
        bsplit(g_yT[o], &g_yT_h[o], &g_yT_l[o]);
    }
}

// ================= bf16-split wmma GEMM (M=128, N=128, K=nch*64) ==============
// 256 threads = 8 warps (4x2), warp tile 32x64 (2x4 wmma 16x16x16 frags).
// A source: [k][m] bf16 hi/lo (col-major for wmma), stride 128.
// W source: [n][k] bf16 hi/lo row-major, stride wstr.
// 3-product split: ah*wh + ah*wl + al*wh, fp32 accumulate.
// SMEM: 2 stages x (Ah|Al|Wh|Wl, 16KB each) = 128KB.
__device__ __forceinline__ void wmma_gemm(
    const __nv_bfloat16* __restrict__ Ah, const __nv_bfloat16* __restrict__ Al,
    const __nv_bfloat16* __restrict__ Wh, const __nv_bfloat16* __restrict__ Wl,
    size_t wstr, int nch, char* smraw, float* Cs, wmma::layout_t clay)
{
    __nv_bfloat16* st = (__nv_bfloat16*)smraw;      // stage s at s*32768 elems
    const int tid = threadIdx.x;
    const int w  = tid >> 5;
    const int wm = w & 3, wn = w >> 2;              // wm 0..3 (32 rows), wn 0..1 (64 cols)

    wmma::fragment<wmma::accumulator,16,16,16,float> acc[2][4];
    #pragma unroll
    for (int i=0;i<2;i++)
        #pragma unroll
        for (int j=0;j<4;j++) wmma::fill_fragment(acc[i][j], 0.f);

    // stage loader: A tiles 64k x 128m ([k][m]), W tiles 128n x 64k ([n][k])
    auto load_stage = [&](int c){
        __nv_bfloat16* sb = st + (c&1)*32768;
        const __nv_bfloat16* asrc[2] = {Ah, Al};
        #pragma unroll
        for (int tA = 0; tA < 2; tA++){
            __nv_bfloat16* tb = sb + tA*8192;
            const __nv_bfloat16* bp = asrc[tA] + (size_t)(c*64)*128;
            for (int q = tid; q < 1024; q += 256){
                int kk = q >> 4, r = q & 15;
                cpa16(tb + kk*128 + r*8, bp + (size_t)kk*128 + r*8);
            }
        }
        const __nv_bfloat16* wsrc[2] = {Wh, Wl};
        #pragma unroll
        for (int tW = 0; tW < 2; tW++){
            __nv_bfloat16* tb = sb + 16384 + tW*8192;
            const __nv_bfloat16* bp = wsrc[tW] + (size_t)c*64;
            for (int q = tid; q < 1024; q += 256){
                int n = q >> 3, i = q & 7;
                cpa16(tb + n*64 + i*8, bp + (size_t)n*wstr + i*8);
            }
        }
        cpcommit();
    };

    load_stage(0);
    if (nch > 1) load_stage(1);
    else cpcommit();   // keep group accounting consistent

    for (int c = 0; c < nch; c++){
        if (c+1 < nch) cpwait1(); else cpwait0();
        __syncthreads();
        __nv_bfloat16* sb = st + (c&1)*32768;
        __nv_bfloat16* At_h = sb;
        __nv_bfloat16* At_l = sb + 8192;
        __nv_bfloat16* Wt_h = sb + 16384;
        __nv_bfloat16* Wt_l = sb + 24576;
        #pragma unroll
        for (int ks = 0; ks < 4; ks++){
            wmma::fragment<wmma::matrix_a,16,16,16,__nv_bfloat16,wmma::col_major> ah[2], al[2];
            #pragma unroll
            for (int i=0;i<2;i++){
                wmma::load_matrix_sync(ah[i], At_h + ks*16*128 + wm*32 + i*16, 128);
                wmma::load_matrix_sync(al[i], At_l + ks*16*128 + wm*32 + i*16, 128);
            }
            #pragma unroll
            for (int j=0;j<4;j++){
                wmma::fragment<wmma::matrix_b,16,16,16,__nv_bfloat16,wmma::col_major> bh, blo;
                wmma::load_matrix_sync(bh,  Wt_h + (wn*64 + j*16)*64 + ks*16, 64);
                wmma::load_matrix_sync(blo, Wt_l + (wn*64 + j*16)*64 + ks*16, 64);
                #pragma unroll
                for (int i=0;i<2;i++){
                    wmma::mma_sync(acc[i][j], ah[i], bh,  acc[i][j]);
                    wmma::mma_sync(acc[i][j], ah[i], blo, acc[i][j]);
                    wmma::mma_sync(acc[i][j], al[i], bh,  acc[i][j]);
                }
            }
        }
        __syncthreads();
        if (c+2 < nch) load_stage(c+2);
    }

    #pragma unroll
    for (int i=0;i<2;i++)
        #pragma unroll
        for (int j=0;j<4;j++){
            int m0 = wm*32 + i*16, n0 = wn*64 + j*16;
            float* p = (clay == wmma::mem_col_major) ? Cs + n0*128 + m0
                                                     : Cs + m0*128 + n0;
            wmma::store_matrix_sync(p, acc[i][j], 128, clay);
        }
    __syncthreads();
}

// ---------------- l2in: D[t][j][b] = feat(t) @ Wihl^T (HMMA) -------------------
__global__ void __launch_bounds__(256,1) k_l2in_mma(const float* __restrict__ bl)
{
    extern __shared__ char smraw[];
    const int tid = threadIdx.x;
    const int t = blockIdx.y, j0 = blockIdx.x*128;
    float* Cs = (float*)smraw;                       // col-major: Cs[j*128+b]

    wmma_gemm(g_featT_h + (size_t)t*K1PAD*BB, g_featT_l + (size_t)t*K1PAD*BB,
              g_wl_h + (size_t)j0*K1PAD,      g_wl_l + (size_t)j0*K1PAD,
              K1PAD, 9, smraw, Cs, wmma::mem_col_major);

    for (int idx = tid; idx < 128*128; idx += 256){
        int j = idx >> 7, b = idx & 127;
        g_l2inT[((size_t)t*G4 + j0 + j)*BB + b] = Cs[idx] + bl[j0 + j];
    }
}

// ---------------- output projection (HMMA) -------------------------------------
__global__ void __launch_bounds__(256,1) k_out_mma(const float* __restrict__ b2,
                                                   float* __restrict__ out)
{
    extern __shared__ char smraw[];
    const int tid = threadIdx.x;
    const int t = blockIdx.x;
    float* Cs = (float*)smraw;                       // row-major: Cs[b*128+j]

    wmma_gemm(g_yT_h + (size_t)t*K2TOT*BB, g_yT_l + (size_t)t*K2TOT*BB,
              g_wo_h, g_wo_l,
              K2TOT, 8, smraw, Cs, wmma::mem_row_major);

    for (int idx = tid; idx < 128*128; idx += 256){
        int b = idx >> 7, j = idx & 127;
        if (j < OUTD) out[((size_t)b*TT + t)*OUTD + j] = Cs[idx] + b2[j];
    }
}

// ================= persistent layer-1 (R6 body: fp32 coalesced writes only) ===
__global__ void __launch_bounds__(512,1)
k_rec1(const float* __restrict__ x,    const float* __restrict__ Wihc,
       const float* __restrict__ Whhc, const float* __restrict__ bc,
       const float* __restrict__ W1,   const float* __restrict__ b1,
       const float* __restrict__ sent, const float* __restrict__ h1c_in)
{
    extern __shared__ float sm[];
    float* Ws    = sm;
    float* As    = Ws + 576*8*4;
    float* sentS = As + 8192;
    float* sh    = sentS + 3840;
    float* sp    = sh + 512;
    float* sphi  = sp + 32;

    const int tid = threadIdx.x;
    const int blk = blockIdx.x;
    const int ht = blk >> 1, bt = blk & 1;
    const int h0 = ht*8;
    const int hl = tid >> 6, bl = tid & 63;
    const int hg = h0 + hl;
    const int bG = bt*64 + bl;
    const int b  = blk;

    for (int idx = tid; idx < 576*8*4; idx += 512){
        int g = idx & 3, h = (idx>>2)&7, k = idx>>5;
        float v = 0.f;
        if (k < K1TOT){
            int j = g*512 + h0 + h;
            v = (k < 63) ? Wihc[(size_t)j*63 + k] : Whhc[(size_t)j*512 + (k-63)];
        }
        Ws[idx] = v;
    }
    for (int idx = tid; idx < SS*CSL; idx += 512)
        sentS[idx] = sent[(size_t)b*SS*CSL + idx];
    if (tid < 32) sp[tid] = 0.f;

    float c1r = h1c_in[(size_t)bG*HH + hg];
    const float bi = bc[hg], bf = bc[512+hg], bg2 = bc[1024+hg], bo = bc[1536+hg];
    __syncthreads();

    const float4* Wsv = (const float4*)Ws;

    for (int t = 0; t < TT; t++){
        const float* h1cur = g_h1T[t&1];

        sh[tid] = h1cur[tid*BB + b];
        __syncthreads();
        {
            int w = tid>>5, lane = tid&31;
            for (int j = w; j < 30; j += 16){
                float s = 0.f;
                #pragma unroll 8
                for (int k = lane; k < 512; k += 32) s += sh[k]*W1[j*512+k];
                #pragma unroll
                for (int o=16;o;o>>=1) s += __shfl_down_sync(0xffffffffu, s, o);
                if (lane == 0){
                    float v = expf(s + b1[j]);
                    if (j >= 20) v -= sp[j];
                    sp[j] = v;
                }
            }
        }
        __syncthreads();
        if (tid < SS){
            float u = (float)(tid+1), acc = 0.f;
            #pragma unroll
            for (int k=0;k<KK;k++){
                float d = sp[20+k] - u;
                acc += sp[k]*expf(-sp[10+k]*d*d);
            }
            sphi[tid] = acc;
        }
        __syncthreads();
        if (tid < CSL){
            float acc = 0.f;
            #pragma unroll 8
            for (int s=0;s<SS;s++) acc += sphi[s]*sentS[s*CSL + tid];
            g_winT[tid*BB + b] = acc;
            g_winsT[((size_t)t*CSL + tid)*BB + b] = acc;
        }
        gbar();

        float gi = bi, gf = bf, gg = bg2, go = bo;

        for (int idx = tid; idx < 63*64; idx += 512){
            int kk = idx >> 6, bb = bt*64 + (idx & 63);
            const float* src = (kk < 3) ? &x[((size_t)bb*TT + t)*IIN + kk]
                                        : &g_winT[(kk-3)*BB + bb];
            cpa4(&As[idx], src);
        }
        cpcommit();
        for (int q = tid; q < 1024; q += 512){
            int kk = q >> 4, r = q & 15;
            cpa16(&As[4096 + kk*64 + r*4], &h1cur[kk*BB + bt*64 + r*4]);
        }
        cpcommit();

        for (int c = 0; c <= 8; c++){
            if (c == 8) cpwait0(); else cpwait1();
            __syncthreads();
            const float* Ab = As + (c&1)*4096;
            const int klen = c ? 64 : 63;
            const int kof  = c ? 63 + (c-1)*64 : 0;
            #pragma unroll 4
            for (int kk = 0; kk < klen; kk++){
                float  a = Ab[kk*64 + bl];
                float4 w = Wsv[(kof+kk)*8 + hl];
                gi += a*w.x; gf += a*w.y; gg += a*w.z; go += a*w.w;
            }
            __syncthreads();
            if (c+2 <= 8){
                int cc = c+2;
                float* dst = As + (c&1)*4096;
                for (int q = tid; q < 1024; q += 512){
                    int kk = q >> 4, r = q & 15;
                    cpa16(&dst[kk*64 + r*4], &h1cur[((cc-1)*64 + kk)*BB + bt*64 + r*4]);
                }
                cpcommit();
            }
        }

        float cn = sigf(gf)*c1r + sigf(gi)*tanhf(gg);
        float hn = sigf(go)*tanhf(cn);
        c1r = cn;
        g_h1T[(t+1)&1][hg*BB + bG] = hn;
        g_hxT[((size_t)t*HH + hg)*BB + bG] = hn;
        if (t == TT-1){
            g_h1f[(size_t)bG*HH + hg] = hn;
            g_c1f[(size_t)bG*HH + hg] = cn;
        }
        gbar();
    }
}

// ================= persistent layer-2 (R6 body; yT now [t][h][b]) =============
__global__ void __launch_bounds__(512,1)
k_rec2(const float* __restrict__ Whhl, const float* __restrict__ h2c_in)
{
    extern __shared__ float sm[];
    float* Ws = sm;
    float* As = Ws + 16384;

    const int tid = threadIdx.x;
    const int blk = blockIdx.x;
    const int ht = blk >> 1, bt = blk & 1;
    const int h0 = ht*8;
    const int hl = tid >> 6, bl = tid & 63;
    const int hg = h0 + hl;
    const int bG = bt*64 + bl;

    for (int idx = tid; idx < 512*8*4; idx += 512){
        int g = idx & 3, h = (idx>>2)&7, k = idx>>5;
        Ws[idx] = Whhl[(size_t)(g*512 + h0 + h)*K2TOT + k];
    }
    float c2r = h2c_in[(size_t)bG*HH + hg];
    __syncthreads();

    const float4* Wsv = (const float4*)Ws;

    for (int t = 0; t < TT; t++){
        const float* h2cur = g_h2T[t&1];

        const float* li = &g_l2inT[(size_t)t*G4*BB];
        float gi = li[(size_t)(hg       )*BB + bG];
        float gf = li[(size_t)(hg +  512)*BB + bG];
        float gg = li[(size_t)(hg + 1024)*BB + bG];
        float go = li[(size_t)(hg + 1536)*BB + bG];

        for (int q = tid; q < 1024; q += 512){
            int kk = q >> 4, r = q & 15;
            cpa16(&As[kk*64 + r*4], &h2cur[kk*BB + bt*64 + r*4]);
        }
        cpcommit();
        for (int q = tid; q < 1024; q += 512){
            int kk = q >> 4, r = q & 15;
            cpa16(&As[4096 + kk*64 + r*4], &h2cur[(64+kk)*BB + bt*64 + r*4]);
        }
        cpcommit();

        for (int c = 0; c <= 7; c++){
            if (c == 7) cpwait0(); else cpwait1();
            __syncthreads();
            const float* Ab = As + (c&1)*4096;
            const int kof = c*64;
            #pragma unroll 4
            for (int kk = 0; kk < 64; kk++){
                float  a = Ab[kk*64 + bl];
                float4 w = Wsv[(kof+kk)*8 + hl];
                gi += a*w.x; gf += a*w.y; gg += a*w.z; go += a*w.w;
            }
            __syncthreads();
            if (c+2 <= 7){
                int cc = c+2;
                float* dst = As + (c&1)*4096;
                for (int q = tid; q < 1024; q += 512){
                    int kk = q >> 4, r = q & 15;
                    cpa16(&dst[kk*64 + r*4], &h2cur[(cc*64 + kk)*BB + bt*64 + r*4]);
                }
                cpcommit();
            }
        }

        float cn = sigf(gf)*c2r + sigf(gi)*tanhf(gg);
        float hn = sigf(go)*tanhf(cn);
        c2r = cn;
        g_h2T[(t+1)&1][hg*BB + bG] = hn;
        g_yT[((size_t)t*HH + hg)*BB + bG] = hn;
        if (t == TT-1){
            g_h2f[(size_t)bG*HH + hg] = hn;
            g_c2f[(size_t)bG*HH + hg] = cn;
        }
        gbar();
    }
}

// ---------------- final states -------------------------------------------------
__global__ void k_states(float* __restrict__ out, int out_size)
{
    const int base = BB*TT*OUTD;
    if (base + 4*BB*HH > out_size) return;
    int i = blockIdx.x*256 + threadIdx.x;
    if (i < BB*HH){
        out[base            + i] = g_h1f[i];
        out[base +   BB*HH  + i] = g_c1f[i];
        out[base + 2*BB*HH  + i] = g_h2f[i];
        out[base + 3*BB*HH  + i] = g_c2f[i];
    }
}

// ---------------- launch -------------------------------------------------------
extern "C" void kernel_launch(void* const* d_in, const int* in_sizes, int n_in,
                              void* d_out, int out_size)
{
    const float* x    = (const float*)d_in[0];
    const float* sent = (const float*)d_in[1];
    const float* h1h  = (const float*)d_in[2];
    const float* h1c  = (const float*)d_in[3];
    const float* h2h  = (const float*)d_in[4];
    const float* h2c  = (const float*)d_in[5];
    const float* Wihc = (const float*)d_in[6];
    const float* Whhc = (const float*)d_in[7];
    const float* bc   = (const float*)d_in[8];
    const float* Wihl = (const float*)d_in[9];
    const float* Whhl = (const float*)d_in[10];
    const float* bl   = (const float*)d_in[11];
    const float* W1   = (const float*)d_in[12];
    const float* b1   = (const float*)d_in[13];
    const float* W2   = (const float*)d_in[14];
    const float* b2   = (const float*)d_in[15];
    float* out = (float*)d_out;

    const int SMEM1 = (18432 + 8192 + 3840 + 512 + 32 + 64) * 4;
    const int SMEM2 = (16384 + 8192) * 4;
    const int SMEMP = 2*65536;                    // 2-stage wmma pipeline (128KB)
    cudaFuncSetAttribute(k_rec1, cudaFuncAttributeMaxDynamicSharedMemorySize, SMEM1);
    cudaFuncSetAttribute(k_rec2, cudaFuncAttributeMaxDynamicSharedMemorySize, SMEM2);
    cudaFuncSetAttribute(k_l2in_mma, cudaFuncAttributeMaxDynamicSharedMemorySize, SMEMP);
    cudaFuncSetAttribute(k_out_mma, cudaFuncAttributeMaxDynamicSharedMemorySize, SMEMP);

    k_init<<<256,256>>>(h1h, h2h);
    k_cvt_w<<<512,256>>>(Wihl, W2);
    k_rec1<<<NBLK,512,SMEM1>>>(x, Wihc, Whhc, bc, W1, b1, sent, h1c);
    k_cvt_feat<<<TT,256>>>(x);
    k_l2in_mma<<<dim3(16,TT),256,SMEMP>>>(bl);
    k_rec2<<<NBLK,512,SMEM2>>>(Whhl, h2c);
    k_cvt_y<<<TT,256>>>();
    k_out_mma<<<TT,256,SMEMP>>>(b2, out);
    k_states<<<(BB*HH+255)/256,256>>>(out, out_size);
}

// round 16
// speedup vs baseline: 1.6483x; 1.5570x over previous
#include <cuda_runtime.h>
#include <cuda_bf16.h>
#include <stdint.h>
#include <math.h>
#include <mma.h>

using namespace nvcuda;

#define BB   128
#define TT   256
#define SS   64
#define IIN  3
#define HH   512
#define KK   10
#define CSL  60
#define OUTD 121
#define G4   2048
#define K1TOT 575
#define K2TOT 512
#define NBLK 128
#define K1PAD 576
#define WS1  584     // W smem row stride (rec1), pad vs 576
#define WS2  520     // W smem row stride (rec2), pad vs 512
#define APAD 40      // A smem tile row stride (32 b + 8 pad)

// ---------------- global scratch ------------------------------------------------
// A operands for recurrent GEMMs: [parity][k][b] bf16 hi/lo (zero-init pads)
__device__ __nv_bfloat16 g_a1h[2][K1PAD*BB];
__device__ __nv_bfloat16 g_a1l[2][K1PAD*BB];
__device__ __nv_bfloat16 g_a2h[2][K2TOT*BB];
__device__ __nv_bfloat16 g_a2l[2][K2TOT*BB];
// feat/y operands for parallel GEMMs: [t][k][b] (row K1TOT..575 stays zero)
__device__ __nv_bfloat16 g_featT_h[(size_t)TT*K1PAD*BB];
__device__ __nv_bfloat16 g_featT_l[(size_t)TT*K1PAD*BB];
__device__ __nv_bfloat16 g_yT_h[(size_t)TT*K2TOT*BB];
__device__ __nv_bfloat16 g_yT_l[(size_t)TT*K2TOT*BB];
// weights for parallel GEMMs
__device__ __nv_bfloat16 g_wl_h[(size_t)G4*K1PAD];
__device__ __nv_bfloat16 g_wl_l[(size_t)G4*K1PAD];
__device__ __nv_bfloat16 g_wo_h[128*K2TOT];
__device__ __nv_bfloat16 g_wo_l[128*K2TOT];
// layer-2 input gates + final states
__device__ float g_l2inT[(size_t)TT*G4*BB];     // [t][j][b]
__device__ float g_h1f[BB*HH], g_c1f[BB*HH], g_h2f[BB*HH], g_c2f[BB*HH];

// ---------------- grid barrier -------------------------------------------------
__device__ unsigned g_cnt = 0;
__device__ volatile unsigned g_gen = 0;

__device__ __forceinline__ void gbar()
{
    __syncthreads();
    if (threadIdx.x == 0){
        unsigned my = g_gen;
        __threadfence();
        if (atomicAdd(&g_cnt, 1u) == NBLK-1u){
            g_cnt = 0;
            __threadfence();
            g_gen = my + 1u;
        } else {
            while (g_gen == my) __nanosleep(64);
        }
        __threadfence();
    }
    __syncthreads();
}

__device__ __forceinline__ float sigf(float x){ return 1.0f/(1.0f+expf(-x)); }

__device__ __forceinline__ void bsplit(float v, __nv_bfloat16* hp, __nv_bfloat16* lp){
    __nv_bfloat16 h = __float2bfloat16(v);
    *hp = h;
    *lp = __float2bfloat16(v - __bfloat162float(h));
}

// ---------------- cp.async helpers --------------------------------------------
__device__ __forceinline__ void cpa16(void* dst, const void* src){
    unsigned d = (unsigned)__cvta_generic_to_shared(dst);
    asm volatile("cp.async.ca.shared.global [%0], [%1], 16;" :: "r"(d), "l"(src));
}
__device__ __forceinline__ void cpcommit(){ asm volatile("cp.async.commit_group;"); }
__device__ __forceinline__ void cpwait0(){ asm volatile("cp.async.wait_group 0;"); }
__device__ __forceinline__ void cpwait1(){ asm volatile("cp.async.wait_group 1;"); }

// ---------------- init: initial states as bf16 hi/lo into parity-0 A buffers ---
__global__ void k_init(const float* __restrict__ h1h, const float* __restrict__ h2h)
{
    int i = blockIdx.x*blockDim.x + threadIdx.x;
    if (i < BB*HH){
        int b = i/HH, h = i%HH;
        bsplit(h1h[i], &g_a1h[0][(63+h)*BB+b], &g_a1l[0][(63+h)*BB+b]);
        bsplit(h2h[i], &g_a2h[0][h*BB+b],      &g_a2l[0][h*BB+b]);
    }
}

// ---------------- convert parallel-GEMM weights to bf16 hi/lo -------------------
__global__ void k_cvt_w(const float* __restrict__ Wihl, const float* __restrict__ W2)
{
    const int n1 = G4*K1TOT;
    const int n2 = OUTD*K2TOT;
    int total = n1 + n2;
    for (int i = blockIdx.x*blockDim.x + threadIdx.x; i < total; i += gridDim.x*blockDim.x){
        if (i < n1){
            int j = i / K1TOT, k = i % K1TOT;
            bsplit(Wihl[i], &g_wl_h[(size_t)j*K1PAD + k], &g_wl_l[(size_t)j*K1PAD + k]);
        } else {
            int i2 = i - n1;
            bsplit(W2[i2], &g_wo_h[i2], &g_wo_l[i2]);
        }
    }
}

// ================= persistent layer-1: HMMA recurrence + fused cell ===========
// 128 blocks = 32 htiles x 4 btiles. Block GEMM tile: M=32 b x N=64 j
// (N = 4 gates x 16 h  ->  block's own cell threads consume all its gates).
// W bf16 hi/lo SMEM-resident; A streamed from parity bf16 buffers.
__global__ void __launch_bounds__(512,1)
k_rec1(const float* __restrict__ x,    const float* __restrict__ Wihc,
       const float* __restrict__ Whhc, const float* __restrict__ bc,
       const float* __restrict__ W1,   const float* __restrict__ b1,
       const float* __restrict__ sent, const float* __restrict__ h1c_in)
{
    extern __shared__ char smem[];
    __nv_bfloat16* Wh = (__nv_bfloat16*)smem;                    // 64 x WS1
    __nv_bfloat16* Wl = (__nv_bfloat16*)(smem + 74752);
    char*  Abase = smem + 149504;                                // 2 stages x 10240B
    float* Cs    = (float*)(smem + 149504);                      // alias, 16KB
    float* sentS = (float*)(smem + 169984);                      // 3840 f
    float* sh    = (float*)(smem + 185344);                      // 512 f
    float* sp    = (float*)(smem + 187392);                      // 32 f
    float* sphi  = (float*)(smem + 187520);                      // 64 f

    const int tid = threadIdx.x;
    const int blk = blockIdx.x;
    const int htile = blk >> 2, btile = blk & 3;
    const int batt  = blk;                       // attention batch for this block
    const int wrp  = tid >> 5;
    const int khalf = wrp >> 3, mi = (wrp >> 2) & 1, ni = wrp & 3;
    const int cl_h = tid >> 5, cl_b = tid & 31;  // cell thread: (h-local, b-local)
    const int hg = htile*16 + cl_h, bG = btile*32 + cl_b;

    // one-time: W tile (bf16 hi/lo) into SMEM; rows n = g*16+hh -> j = g*512+htile*16+hh
    for (int idx = tid; idx < 64*WS1; idx += 512){
        int n = idx / WS1, k = idx - n*WS1;
        float v = 0.f;
        if (k < K1TOT){
            int j = (n>>4)*512 + htile*16 + (n&15);
            v = (k < 63) ? Wihc[(size_t)j*63 + k] : Whhc[(size_t)j*512 + (k-63)];
        }
        bsplit(v, &Wh[idx], &Wl[idx]);
    }
    for (int idx = tid; idx < SS*CSL; idx += 512)
        sentS[idx] = sent[(size_t)batt*SS*CSL + idx];
    if (tid < 32) sp[tid] = 0.f;

    float c1r = h1c_in[(size_t)bG*HH + hg];
    const float bi0=bc[hg], bi1=bc[512+hg], bi2=bc[1024+hg], bi3=bc[1536+hg];
    __syncthreads();

    for (int t = 0; t < TT; t++){
        const int p = t & 1;
        const __nv_bfloat16* Ahg = g_a1h[p];
        const __nv_bfloat16* Alg = g_a1l[p];

        // ---- phase A: write x(t) rows, attention(t), write win rows ----------
        if (tid < IIN){
            float v = x[((size_t)batt*TT + t)*IIN + tid];
            bsplit(v, &g_a1h[p][tid*BB+batt], &g_a1l[p][tid*BB+batt]);
            size_t fo = (size_t)t*K1PAD*BB + tid*BB + batt;
            bsplit(v, &g_featT_h[fo], &g_featT_l[fo]);
        }
        sh[tid] = __bfloat162float(Ahg[(63+tid)*BB + batt])
                + __bfloat162float(Alg[(63+tid)*BB + batt]);
        __syncthreads();
        {
            int w2 = tid>>5, lane = tid&31;
            for (int j = w2; j < 30; j += 16){
                float s = 0.f;
                #pragma unroll 8
                for (int k = lane; k < 512; k += 32) s += sh[k]*W1[j*512+k];
                #pragma unroll
                for (int o=16;o;o>>=1) s += __shfl_down_sync(0xffffffffu, s, o);
                if (lane == 0){
                    float v = expf(s + b1[j]);
                    if (j >= 20) v -= sp[j];
                    sp[j] = v;
                }
            }
        }
        __syncthreads();
        if (tid < SS){
            float u = (float)(tid+1), acc = 0.f;
            #pragma unroll
            for (int k=0;k<KK;k++){
                float d = sp[20+k] - u;
                acc += sp[k]*expf(-sp[10+k]*d*d);
            }
            sphi[tid] = acc;
        }
        __syncthreads();
        if (tid < CSL){
            float acc = 0.f;
            #pragma unroll 8
            for (int s=0;s<SS;s++) acc += sphi[s]*sentS[s*CSL + tid];
            bsplit(acc, &g_a1h[p][(3+tid)*BB+batt], &g_a1l[p][(3+tid)*BB+batt]);
            size_t fo = (size_t)t*K1PAD*BB + (3+tid)*BB + batt;
            bsplit(acc, &g_featT_h[fo], &g_featT_l[fo]);
        }
        gbar();

        // ---- phase B: HMMA GEMM (K=576, 9 chunks of 64) + fused cell ---------
        wmma::fragment<wmma::accumulator,16,16,16,float> acc;
        wmma::fill_fragment(acc, 0.f);

        auto load_stage = [&](int c){
            int op = tid >> 8, r = tid & 255;
            int kk = r >> 2, seg = r & 3;
            const __nv_bfloat16* src = (op ? Alg : Ahg)
                + (size_t)(c*64+kk)*BB + btile*32 + seg*8;
            char* dst = Abase + (c&1)*10240 + op*5120 + kk*(APAD*2) + seg*16;
            cpa16(dst, src);
            cpcommit();
        };
        load_stage(0);
        load_stage(1);

        for (int c = 0; c < 9; c++){
            if (c+1 < 9) cpwait1(); else cpwait0();
            __syncthreads();
            const __nv_bfloat16* Ast_h = (const __nv_bfloat16*)(Abase + (c&1)*10240);
            const __nv_bfloat16* Ast_l = (const __nv_bfloat16*)(Abase + (c&1)*10240 + 5120);
            #pragma unroll
            for (int s2 = 0; s2 < 2; s2++){
                int koff = khalf*32 + s2*16;
                int kg   = c*64 + koff;
                wmma::fragment<wmma::matrix_a,16,16,16,__nv_bfloat16,wmma::col_major> fah, fal;
                wmma::load_matrix_sync(fah, Ast_h + koff*APAD + mi*16, APAD);
                wmma::load_matrix_sync(fal, Ast_l + koff*APAD + mi*16, APAD);
                wmma::fragment<wmma::matrix_b,16,16,16,__nv_bfloat16,wmma::col_major> fbh, fbl;
                wmma::load_matrix_sync(fbh, Wh + (size_t)ni*16*WS1 + kg, WS1);
                wmma::load_matrix_sync(fbl, Wl + (size_t)ni*16*WS1 + kg, WS1);
                wmma::mma_sync(acc, fah, fbh, acc);
                wmma::mma_sync(acc, fah, fbl, acc);
                wmma::mma_sync(acc, fal, fbh, acc);
            }
            __syncthreads();
            if (c+2 < 9) load_stage(c+2);
        }
        wmma::store_matrix_sync(Cs + khalf*2048 + ni*16*32 + mi*16, acc, 32,
                                wmma::mem_col_major);
        __syncthreads();

        // fused cell: gates for (hg, bG) from this block's Cs (sum K-halves)
        float g0 = Cs[(0*16+cl_h)*32 + cl_b] + Cs[2048 + (0*16+cl_h)*32 + cl_b] + bi0;
        float g1 = Cs[(1*16+cl_h)*32 + cl_b] + Cs[2048 + (1*16+cl_h)*32 + cl_b] + bi1;
        float g2 = Cs[(2*16+cl_h)*32 + cl_b] + Cs[2048 + (2*16+cl_h)*32 + cl_b] + bi2;
        float g3 = Cs[(3*16+cl_h)*32 + cl_b] + Cs[2048 + (3*16+cl_h)*32 + cl_b] + bi3;
        float cn = sigf(g1)*c1r + sigf(g0)*tanhf(g2);
        float hn = sigf(g3)*tanhf(cn);
        c1r = cn;
        __nv_bfloat16 hhi, hlo;
        bsplit(hn, &hhi, &hlo);
        g_a1h[p^1][(63+hg)*BB + bG] = hhi;
        g_a1l[p^1][(63+hg)*BB + bG] = hlo;
        size_t fo = (size_t)t*K1PAD*BB + (63+hg)*BB + bG;
        g_featT_h[fo] = hhi;
        g_featT_l[fo] = hlo;
        if (t == TT-1){
            g_h1f[(size_t)bG*HH + hg] = hn;
            g_c1f[(size_t)bG*HH + hg] = cn;
        }
        gbar();
    }
}

// ================= persistent layer-2: HMMA recurrence + fused cell ===========
__global__ void __launch_bounds__(512,1)
k_rec2(const float* __restrict__ Whhl, const float* __restrict__ h2c_in)
{
    extern __shared__ char smem[];
    __nv_bfloat16* Wh = (__nv_bfloat16*)smem;                    // 64 x WS2
    __nv_bfloat16* Wl = (__nv_bfloat16*)(smem + 66560);
    char*  Abase = smem + 133120;                                // 2 stages x 10240B
    float* Cs    = (float*)(smem + 133120);                      // alias, 16KB

    const int tid = threadIdx.x;
    const int blk = blockIdx.x;
    const int htile = blk >> 2, btile = blk & 3;
    const int wrp  = tid >> 5;
    const int khalf = wrp >> 3, mi = (wrp >> 2) & 1, ni = wrp & 3;
    const int cl_h = tid >> 5, cl_b = tid & 31;
    const int hg = htile*16 + cl_h, bG = btile*32 + cl_b;

    for (int idx = tid; idx < 64*WS2; idx += 512){
        int n = idx / WS2, k = idx - n*WS2;
        float v = 0.f;
        if (k < K2TOT){
            int j = (n>>4)*512 + htile*16 + (n&15);
            v = Whhl[(size_t)j*K2TOT + k];
        }
        bsplit(v, &Wh[idx], &Wl[idx]);
    }
    float c2r = h2c_in[(size_t)bG*HH + hg];
    __syncthreads();

    for (int t = 0; t < TT; t++){
        const int p = t & 1;
        const __nv_bfloat16* Ahg = g_a2h[p];
        const __nv_bfloat16* Alg = g_a2l[p];

        wmma::fragment<wmma::accumulator,16,16,16,float> acc;
        wmma::fill_fragment(acc, 0.f);

        auto load_stage = [&](int c){
            int op = tid >> 8, r = tid & 255;
            int kk = r >> 2, seg = r & 3;
            const __nv_bfloat16* src = (op ? Alg : Ahg)
                + (size_t)(c*64+kk)*BB + btile*32 + seg*8;
            char* dst = Abase + (c&1)*10240 + op*5120 + kk*(APAD*2) + seg*16;
            cpa16(dst, src);
            cpcommit();
        };
        load_stage(0);
        load_stage(1);

        for (int c = 0; c < 8; c++){
            if (c+1 < 8) cpwait1(); else cpwait0();
            __syncthreads();
            const __nv_bfloat16* Ast_h = (const __nv_bfloat16*)(Abase + (c&1)*10240);
            const __nv_bfloat16* Ast_l = (const __nv_bfloat16*)(Abase + (c&1)*10240 + 5120);
            #pragma unroll
            for (int s2 = 0; s2 < 2; s2++){
                int koff = khalf*32 + s2*16;
                int kg   = c*64 + koff;
                wmma::fragment<wmma::matrix_a,16,16,16,__nv_bfloat16,wmma::col_major> fah, fal;
                wmma::load_matrix_sync(fah, Ast_h + koff*APAD + mi*16, APAD);
                wmma::load_matrix_sync(fal, Ast_l + koff*APAD + mi*16, APAD);
                wmma::fragment<wmma::matrix_b,16,16,16,__nv_bfloat16,wmma::col_major> fbh, fbl;
                wmma::load_matrix_sync(fbh, Wh + (size_t)ni*16*WS2 + kg, WS2);
                wmma::load_matrix_sync(fbl, Wl + (size_t)ni*16*WS2 + kg, WS2);
                wmma::mma_sync(acc, fah, fbh, acc);
                wmma::mma_sync(acc, fah, fbl, acc);
                wmma::mma_sync(acc, fal, fbh, acc);
            }
            __syncthreads();
            if (c+2 < 8) load_stage(c+2);
        }
        wmma::store_matrix_sync(Cs + khalf*2048 + ni*16*32 + mi*16, acc, 32,
                                wmma::mem_col_major);
        __syncthreads();

        const float* li = g_l2inT + (size_t)t*G4*BB;
        float g0 = Cs[(0*16+cl_h)*32+cl_b] + Cs[2048+(0*16+cl_h)*32+cl_b]
                 + li[(size_t)(hg       )*BB + bG];
        float g1 = Cs[(1*16+cl_h)*32+cl_b] + Cs[2048+(1*16+cl_h)*32+cl_b]
                 + li[(size_t)(hg +  512)*BB + bG];
        float g2 = Cs[(2*16+cl_h)*32+cl_b] + Cs[2048+(2*16+cl_h)*32+cl_b]
                 + li[(size_t)(hg + 1024)*BB + bG];
        float g3 = Cs[(3*16+cl_h)*32+cl_b] + Cs[2048+(3*16+cl_h)*32+cl_b]
                 + li[(size_t)(hg + 1536)*BB + bG];
        float cn = sigf(g1)*c2r + sigf(g0)*tanhf(g2);
        float hn = sigf(g3)*tanhf(cn);
        c2r = cn;
        __nv_bfloat16 hhi, hlo;
        bsplit(hn, &hhi, &hlo);
        g_a2h[p^1][hg*BB + bG] = hhi;
        g_a2l[p^1][hg*BB + bG] = hlo;
        size_t yo = (size_t)t*K2TOT*BB + hg*BB + bG;
        g_yT_h[yo] = hhi;
        g_yT_l[yo] = hlo;
        if (t == TT-1){
            g_h2f[(size_t)bG*HH + hg] = hn;
            g_c2f[(size_t)bG*HH + hg] = cn;
        }
        gbar();
    }
}

// ================= parallel bf16-split wmma GEMM (unchanged, passing) =========
__device__ __forceinline__ void wmma_gemm(
    const __nv_bfloat16* __restrict__ Ah, const __nv_bfloat16* __restrict__ Al,
    const __nv_bfloat16* __restrict__ Wh, const __nv_bfloat16* __restrict__ Wl,
    size_t wstr, int nch, char* smraw, float* Cs, wmma::layout_t clay)
{
    __nv_bfloat16* st = (__nv_bfloat16*)smraw;
    const int tid = threadIdx.x;
    const int w  = tid >> 5;
    const int wm = w & 3, wn = w >> 2;

    wmma::fragment<wmma::accumulator,16,16,16,float> acc[2][4];
    #pragma unroll
    for (int i=0;i<2;i++)
        #pragma unroll
        for (int j=0;j<4;j++) wmma::fill_fragment(acc[i][j], 0.f);

    auto load_stage = [&](int c){
        __nv_bfloat16* sb = st + (c&1)*32768;
        const __nv_bfloat16* asrc[2] = {Ah, Al};
        #pragma unroll
        for (int tA = 0; tA < 2; tA++){
            __nv_bfloat16* tb = sb + tA*8192;
            const __nv_bfloat16* bp = asrc[tA] + (size_t)(c*64)*128;
            for (int q = tid; q < 1024; q += 256){
                int kk = q >> 4, r = q & 15;
                cpa16(tb + kk*128 + r*8, bp + (size_t)kk*128 + r*8);
            }
        }
        const __nv_bfloat16* wsrc[2] = {Wh, Wl};
        #pragma unroll
        for (int tW = 0; tW < 2; tW++){
            __nv_bfloat16* tb = sb + 16384 + tW*8192;
            const __nv_bfloat16* bp = wsrc[tW] + (size_t)c*64;
            for (int q = tid; q < 1024; q += 256){
                int n = q >> 3, i = q & 7;
                cpa16(tb + n*64 + i*8, bp + (size_t)n*wstr + i*8);
            }
        }
        cpcommit();
    };

    load_stage(0);
    if (nch > 1) load_stage(1);
    else cpcommit();

    for (int c = 0; c < nch; c++){
        if (c+1 < nch) cpwait1(); else cpwait0();
        __syncthreads();
        __nv_bfloat16* sb = st + (c&1)*32768;
        __nv_bfloat16* At_h = sb;
        __nv_bfloat16* At_l = sb + 8192;
        __nv_bfloat16* Wt_h = sb + 16384;
        __nv_bfloat16* Wt_l = sb + 24576;
        #pragma unroll
        for (int ks = 0; ks < 4; ks++){
            wmma::fragment<wmma::matrix_a,16,16,16,__nv_bfloat16,wmma::col_major> ah[2], al[2];
            #pragma unroll
            for (int i=0;i<2;i++){
                wmma::load_matrix_sync(ah[i], At_h + ks*16*128 + wm*32 + i*16, 128);
                wmma::load_matrix_sync(al[i], At_l + ks*16*128 + wm*32 + i*16, 128);
            }
            #pragma unroll
            for (int j=0;j<4;j++){
                wmma::fragment<wmma::matrix_b,16,16,16,__nv_bfloat16,wmma::col_major> bh, blo;
                wmma::load_matrix_sync(bh,  Wt_h + (wn*64 + j*16)*64 + ks*16, 64);
                wmma::load_matrix_sync(blo, Wt_l + (wn*64 + j*16)*64 + ks*16, 64);
                #pragma unroll
                for (int i=0;i<2;i++){
                    wmma::mma_sync(acc[i][j], ah[i], bh,  acc[i][j]);
                    wmma::mma_sync(acc[i][j], ah[i], blo, acc[i][j]);
                    wmma::mma_sync(acc[i][j], al[i], bh,  acc[i][j]);
                }
            }
        }
        __syncthreads();
        if (c+2 < nch) load_stage(c+2);
    }

    #pragma unroll
    for (int i=0;i<2;i++)
        #pragma unroll
        for (int j=0;j<4;j++){
            int m0 = wm*32 + i*16, n0 = wn*64 + j*16;
            float* p = (clay == wmma::mem_col_major) ? Cs + n0*128 + m0
                                                     : Cs + m0*128 + n0;
            wmma::store_matrix_sync(p, acc[i][j], 128, clay);
        }
    __syncthreads();
}

// ---------------- l2in: D[t][j][b] = feat(t) @ Wihl^T --------------------------
__global__ void __launch_bounds__(256,1) k_l2in_mma(const float* __restrict__ bl)
{
    extern __shared__ char smraw[];
    const int tid = threadIdx.x;
    const int t = blockIdx.y, j0 = blockIdx.x*128;
    float* Cs = (float*)smraw;

    wmma_gemm(g_featT_h + (size_t)t*K1PAD*BB, g_featT_l + (size_t)t*K1PAD*BB,
              g_wl_h + (size_t)j0*K1PAD,      g_wl_l + (size_t)j0*K1PAD,
              K1PAD, 9, smraw, Cs, wmma::mem_col_major);

    for (int idx = tid; idx < 128*128; idx += 256){
        int j = idx >> 7, b = idx & 127;
        g_l2inT[((size_t)t*G4 + j0 + j)*BB + b] = Cs[idx] + bl[j0 + j];
    }
}

// ---------------- output projection --------------------------------------------
__global__ void __launch_bounds__(256,1) k_out_mma(const float* __restrict__ b2,
                                                   float* __restrict__ out)
{
    extern __shared__ char smraw[];
    const int tid = threadIdx.x;
    const int t = blockIdx.x;
    float* Cs = (float*)smraw;

    wmma_gemm(g_yT_h + (size_t)t*K2TOT*BB, g_yT_l + (size_t)t*K2TOT*BB,
              g_wo_h, g_wo_l,
              K2TOT, 8, smraw, Cs, wmma::mem_row_major);

    for (int idx = tid; idx < 128*128; idx += 256){
        int b = idx >> 7, j = idx & 127;
        if (j < OUTD) out[((size_t)b*TT + t)*OUTD + j] = Cs[idx] + b2[j];
    }
}

// ---------------- final states -------------------------------------------------
__global__ void k_states(float* __restrict__ out, int out_size)
{
    const int base = BB*TT*OUTD;
    if (base + 4*BB*HH > out_size) return;
    int i = blockIdx.x*256 + threadIdx.x;
    if (i < BB*HH){
        out[base            + i] = g_h1f[i];
        out[base +   BB*HH  + i] = g_c1f[i];
        out[base + 2*BB*HH  + i] = g_h2f[i];
        out[base + 3*BB*HH  + i] = g_c2f[i];
    }
}

// ---------------- launch -------------------------------------------------------
extern "C" void kernel_launch(void* const* d_in, const int* in_sizes, int n_in,
                              void* d_out, int out_size)
{
    const float* x    = (const float*)d_in[0];
    const float* sent = (const float*)d_in[1];
    const float* h1h  = (const float*)d_in[2];
    const float* h1c  = (const float*)d_in[3];
    const float* h2h  = (const float*)d_in[4];
    const float* h2c  = (const float*)d_in[5];
    const float* Wihc = (const float*)d_in[6];
    const float* Whhc = (const float*)d_in[7];
    const float* bc   = (const float*)d_in[8];
    const float* Wihl = (const float*)d_in[9];
    const float* Whhl = (const float*)d_in[10];
    const float* bl   = (const float*)d_in[11];
    const float* W1   = (const float*)d_in[12];
    const float* b1   = (const float*)d_in[13];
    const float* W2   = (const float*)d_in[14];
    const float* b2   = (const float*)d_in[15];
    float* out = (float*)d_out;

    const int SMEM1 = 187776;     // rec1: W(146K) + A-stages/Cs(20K) + attn(17.4K)
    const int SMEM2 = 153600;     // rec2: W(130K) + A-stages/Cs(20K)
    const int SMEMP = 2*65536;    // parallel GEMM pipeline
    cudaFuncSetAttribute(k_rec1, cudaFuncAttributeMaxDynamicSharedMemorySize, SMEM1);
    cudaFuncSetAttribute(k_rec2, cudaFuncAttributeMaxDynamicSharedMemorySize, SMEM2);
    cudaFuncSetAttribute(k_l2in_mma, cudaFuncAttributeMaxDynamicSharedMemorySize, SMEMP);
    cudaFuncSetAttribute(k_out_mma, cudaFuncAttributeMaxDynamicSharedMemorySize, SMEMP);

    k_init<<<256,256>>>(h1h, h2h);
    k_cvt_w<<<512,256>>>(Wihl, W2);
    k_rec1<<<NBLK,512,SMEM1>>>(x, Wihc, Whhc, bc, W1, b1, sent, h1c);
    k_l2in_mma<<<dim3(16,TT),256,SMEMP>>>(bl);
    k_rec2<<<NBLK,512,SMEM2>>>(Whhl, h2c);
    k_out_mma<<<TT,256,SMEMP>>>(b2, out);
    k_states<<<(BB*HH+255)/256,256>>>(out, out_size);
}